// round 15
// baseline (speedup 1.0000x reference)
#include <cuda_runtime.h>
#include <cuda_bf16.h>
#include <math.h>
#include <stdint.h>

// Problem constants (nondecayRNN: B=256, T=512, I=128, H=1024, O=128)
namespace {
constexpr int kB = 256;
constexpr int kT = 512;
constexpr int kI = 128;
constexpr int kH = 1024;
constexpr int kO = 128;

constexpr int kGroups        = 8;                 // independent batch groups
constexpr int kBc            = kB / kGroups;      // 32 batch rows / group
constexpr int kTilesPerGroup = 16;                // N-tiles of 64 over H
constexpr int kTN            = kH / kTilesPerGroup; // 64

constexpr int kChunk  = 64;        // K chunk == one producer tile's columns
constexpr int kNCh    = kH / kChunk;   // 16
constexpr int kStages = 4;         // cp.async pipeline depth

// Recurrence SMEM layout (bytes)
constexpr int SBHI_STRIDE = 1032;  // bf16 elems per n-row, padded (1024+8)
constexpr int SCH_STRIDE  = 72;    // bf16 elems per row in chunk bufs (64+8)
constexpr int A_PL      = 32 * SCH_STRIDE * 2;        // 4608 per A plane
constexpr int BLO_OFF   = 2 * A_PL;                   // 9216
constexpr int BUF_BYTES = 2 * A_PL + 64 * SCH_STRIDE * 2;  // 18432
constexpr int BHI_BYTES = 64 * SBHI_STRIDE * 2;       // 132096 persistent
constexpr int SMEM_TOTAL = BHI_BYTES + kStages * BUF_BYTES; // 205824

// xin / output GEMM config: CTA = 128 rows x 128 cols, padded stride 72
constexpr int GST   = 72;
constexpr int GPA   = 128 * GST * 2;       // 18432 B per plane tile
constexpr int GBUF  = 4 * GPA;             // Ahi|Alo|Bhi|Blo = 73728
constexpr int GSMEM = 2 * GBUF;            // 147456
}

// ---------------------------------------------------------------------------
// Device scratch (static __device__ arrays — no runtime allocation)
// ---------------------------------------------------------------------------
__device__ unsigned int   g_flag[kGroups * kTilesPerGroup];  // per-tile steps
__device__ __nv_bfloat16  g_Wr[2][kH * kH];                 // Wrec  [hi/lo]
__device__ __nv_bfloat16  g_Wi[2][kH * kI];                 // W_in  [hi/lo]
__device__ __nv_bfloat16  g_Wout[2][kO * kH];               // W_out [hi/lo]
__device__ __nv_bfloat16  g_xs[2][(size_t)kB * kT * kI];    // x     [hi/lo]
__device__ float          g_xin[(size_t)kB * kT * kH];      // xin+b_in (fp32)
__device__ __nv_bfloat16  g_hb[2][(size_t)kB * kT * kH];    // hiddens planes

// ---------------------------------------------------------------------------
// PTX helpers
// ---------------------------------------------------------------------------
__device__ __forceinline__ uint32_t smem_u32(const void* p) {
    return (uint32_t)__cvta_generic_to_shared(p);
}
__device__ __forceinline__ void cpa16(uint32_t dst, const void* src) {
    asm volatile("cp.async.cg.shared.global [%0], [%1], 16;"
                 :: "r"(dst), "l"(src) : "memory");
}
__device__ __forceinline__ void cp_commit() {
    asm volatile("cp.async.commit_group;" ::: "memory");
}
__device__ __forceinline__ void cp_wait0() {
    asm volatile("cp.async.wait_group 0;" ::: "memory");
}
__device__ __forceinline__ void cp_wait1() {
    asm volatile("cp.async.wait_group 1;" ::: "memory");
}
__device__ __forceinline__ void cp_wait2() {
    asm volatile("cp.async.wait_group 2;" ::: "memory");
}
__device__ __forceinline__ void ldm4(uint32_t* r, uint32_t addr) {
    asm volatile("ldmatrix.sync.aligned.m8n8.x4.shared.b16 {%0,%1,%2,%3}, [%4];"
                 : "=r"(r[0]), "=r"(r[1]), "=r"(r[2]), "=r"(r[3]) : "r"(addr));
}
__device__ __forceinline__ void mma16816(float* d, const uint32_t* a,
                                         uint32_t b0, uint32_t b1) {
    asm volatile(
        "mma.sync.aligned.m16n8k16.row.col.f32.bf16.bf16.f32 "
        "{%0,%1,%2,%3}, {%4,%5,%6,%7}, {%8,%9}, {%0,%1,%2,%3};"
        : "+f"(d[0]), "+f"(d[1]), "+f"(d[2]), "+f"(d[3])
        : "r"(a[0]), "r"(a[1]), "r"(a[2]), "r"(a[3]), "r"(b0), "r"(b1));
}
__device__ __forceinline__ void split_bf16(float v, __nv_bfloat16& hi,
                                           __nv_bfloat16& lo) {
    hi = __float2bfloat16(v);
    lo = __float2bfloat16(v - __bfloat162float(hi));
}
__device__ __forceinline__ void barrier_arrive(unsigned int* p) {
    asm volatile("red.release.gpu.global.add.u32 [%0], %1;"
                 :: "l"(p), "r"(1u) : "memory");
}
__device__ __forceinline__ unsigned int ld_acquire(const unsigned int* p) {
    unsigned int v;
    asm volatile("ld.acquire.gpu.global.u32 %0, [%1];"
                 : "=r"(v) : "l"(p) : "memory");
    return v;
}

// ---------------------------------------------------------------------------
// Prepass: split Wrec / W_in / W_out into bf16 hi/lo planes; reset flags.
// ---------------------------------------------------------------------------
__global__ void convert_w_kernel(const float* __restrict__ Wrec,
                                 const float* __restrict__ W_in,
                                 const float* __restrict__ W_out) {
    if (blockIdx.x == 0 && threadIdx.x < kGroups * kTilesPerGroup)
        g_flag[threadIdx.x] = 0u;
    const int stride = gridDim.x * blockDim.x;
    const int base   = blockIdx.x * blockDim.x + threadIdx.x;

    for (int idx = base; idx < kH * kH; idx += stride) {
        __nv_bfloat16 hi, lo;
        split_bf16(Wrec[idx], hi, lo);
        g_Wr[0][idx] = hi;
        g_Wr[1][idx] = lo;
    }
    for (int idx = base; idx < kH * kI; idx += stride) {
        __nv_bfloat16 hi, lo;
        split_bf16(W_in[idx], hi, lo);
        g_Wi[0][idx] = hi;
        g_Wi[1][idx] = lo;
    }
    for (int idx = base; idx < kO * kH; idx += stride) {
        __nv_bfloat16 hi, lo;
        split_bf16(W_out[idx], hi, lo);
        g_Wout[0][idx] = hi;
        g_Wout[1][idx] = lo;
    }
}

// Prepass: split x into bf16 hi/lo planes (same [B][T][I] layout).
__global__ void convert_x_kernel(const float* __restrict__ x) {
    const int n4 = (kB * kT * kI) / 4;
    __nv_bfloat162* xh = reinterpret_cast<__nv_bfloat162*>(g_xs[0]);
    __nv_bfloat162* xl = reinterpret_cast<__nv_bfloat162*>(g_xs[1]);
    for (int i = blockIdx.x * blockDim.x + threadIdx.x; i < n4;
         i += gridDim.x * blockDim.x) {
        float4 v = reinterpret_cast<const float4*>(x)[i];
        float vs[4] = {v.x, v.y, v.z, v.w};
        __nv_bfloat16 hi[4], lo[4];
#pragma unroll
        for (int k = 0; k < 4; ++k) split_bf16(vs[k], hi[k], lo[k]);
        __nv_bfloat162 p;
        p.x = hi[0]; p.y = hi[1]; xh[2 * i]     = p;
        p.x = hi[2]; p.y = hi[3]; xh[2 * i + 1] = p;
        p.x = lo[0]; p.y = lo[1]; xl[2 * i]     = p;
        p.x = lo[2]; p.y = lo[3]; xl[2 * i + 1] = p;
    }
}

// ---------------------------------------------------------------------------
// xin GEMM: g_xin[r, j] = x[r] @ W_in^T[j] + b_in[j] (unchanged).
// ---------------------------------------------------------------------------
__global__ __launch_bounds__(256, 1)
void xin_gemm_tc(const float* __restrict__ b_in)
{
    extern __shared__ char smem[];
    const int tid = threadIdx.x;
    const int w   = tid >> 5;
    const int l   = tid & 31;
    const int m   = l >> 3;
    const int cb  = blockIdx.x & 7;
    const size_t r0g = (size_t)(blockIdx.x >> 3) * 128;
    const int j0  = cb * 128;

    const int aoff = ((w * 16 + (l & 7) + (m & 1) * 8) * GST + (m >> 1) * 8) * 2;
    const int boff = (((m >> 1) * 8 + (l & 7)) * GST + (m & 1) * 8) * 2;
    const uint32_t bufU[2] = { smem_u32(smem), smem_u32(smem + GBUF) };

    float acc[16][4];
#pragma unroll
    for (int j = 0; j < 16; ++j)
#pragma unroll
        for (int v = 0; v < 4; ++v) acc[j][v] = 0.0f;

    auto load_chunk = [&](int c, uint32_t bu) {
        const int k0 = c * 64;
#pragma unroll
        for (int jj = 0; jj < 8; ++jj) {
            int idx = tid + jj * 256;
            int plane = idx >> 10, rem = idx & 1023;
            int row = rem >> 3, seg = rem & 7;
            cpa16(bu + plane * GPA + (row * GST + seg * 8) * 2,
                  &g_xs[plane][(r0g + row) * kI + k0 + seg * 8]);
        }
#pragma unroll
        for (int jj = 0; jj < 8; ++jj) {
            int idx = tid + jj * 256;
            int plane = idx >> 10, rem = idx & 1023;
            int row = rem >> 3, seg = rem & 7;
            cpa16(bu + 2 * GPA + plane * GPA + (row * GST + seg * 8) * 2,
                  &g_Wi[plane][(size_t)(j0 + row) * kI + k0 + seg * 8]);
        }
    };

    load_chunk(0, bufU[0]);
    cp_commit();
    load_chunk(1, bufU[1]);
    cp_commit();

#pragma unroll 1
    for (int c = 0; c < 2; ++c) {
        if (c == 0) cp_wait1(); else cp_wait0();
        __syncthreads();
        const uint32_t bu  = bufU[c];
        const uint32_t aHi = bu + aoff;
        const uint32_t aLo = bu + GPA + aoff;
        const uint32_t bHi = bu + 2 * GPA + boff;
        const uint32_t bLo = bu + 3 * GPA + boff;
#pragma unroll
        for (int kk = 0; kk < 4; ++kk) {
            uint32_t Ah[4], Al[4];
            ldm4(Ah, aHi + kk * 32);
            ldm4(Al, aLo + kk * 32);
#pragma unroll
            for (int nf = 0; nf < 8; ++nf) {
                uint32_t Bh[4], Bl[4];
                ldm4(Bh, bHi + nf * (16 * GST * 2) + kk * 32);
                ldm4(Bl, bLo + nf * (16 * GST * 2) + kk * 32);
                mma16816(acc[2 * nf],     Ah, Bh[0], Bh[1]);
                mma16816(acc[2 * nf + 1], Ah, Bh[2], Bh[3]);
                mma16816(acc[2 * nf],     Ah, Bl[0], Bl[1]);
                mma16816(acc[2 * nf + 1], Ah, Bl[2], Bl[3]);
                mma16816(acc[2 * nf],     Al, Bh[0], Bh[1]);
                mma16816(acc[2 * nf + 1], Al, Bh[2], Bh[3]);
            }
        }
    }

#pragma unroll
    for (int half = 0; half < 2; ++half) {
        const size_t row = r0g + w * 16 + (l >> 2) + half * 8;
#pragma unroll
        for (int j = 0; j < 16; ++j) {
            const int col = j * 8 + 2 * (l & 3);
            float2 o;
            o.x = acc[j][2 * half + 0] + b_in[j0 + col];
            o.y = acc[j][2 * half + 1] + b_in[j0 + col + 1];
            *reinterpret_cast<float2*>(&g_xin[row * kH + j0 + col]) = o;
        }
    }
}

// ---------------------------------------------------------------------------
// Tensor-core recurrence: per-tile dataflow flags + ROTATED chunk order.
// CTA jt of a group processes chunks cc = (jt + i) % 16, i = 0..15:
//   i=0 is the CTA's OWN tile (flag trivially satisfied, zero wait);
//   the wait on tile jt+d occurs d-3 chunks into the step, so producer
//   skew is absorbed progressively around the ring — no convoy (R12's bug),
//   no monolithic barrier release->observe on the critical path (R9's cost).
// 4-stage cp.async pipeline of 64-wide chunks, 1 __syncthreads/chunk,
// fragment double-buffering in the MMA loop. Epilogue publishes this tile's
// step count via release-arrive on its own flag.
// Grid: 128 CTAs = 8 groups x 16 tiles, 256 thr (8 warps = 2M x 4N, m16n16).
// 3-pass bf16 split: D += Ah*Bh + Ah*Bl + Al*Bh. Wrec_hi SMEM-persistent.
// ---------------------------------------------------------------------------
__global__ __launch_bounds__(256, 1)
void rnn_rec_tc(float* __restrict__ hid)   // [B, T, H] fp32 output
{
    extern __shared__ char smem[];
    char* sBhi = smem;                     // persistent Wrec_hi [64][1032]
    char* sBuf = smem + BHI_BYTES;         // 4 stage buffers

    const int tid = threadIdx.x;
    const int g   = blockIdx.x / kTilesPerGroup;
    const int jt  = blockIdx.x % kTilesPerGroup;
    const int j0  = jt * kTN;
    const int b0  = g * kBc;
    const int w   = tid >> 5;
    const int l   = tid & 31;
    const int r0  = (w >> 2) * 16;   // A-row base within 32-row tile
    const int c0  = (w & 3) * 16;    // n base within 64-col tile

    unsigned int* flags = &g_flag[g * kTilesPerGroup];

    // ---- persistent Wrec_hi slice load: 64 rows x 128 segs of 8 ----
#pragma unroll
    for (int j = 0; j < 32; ++j) {
        int idx = tid + j * 256;
        int row = idx >> 7, seg = idx & 127;
        cpa16(smem_u32(sBhi + (row * SBHI_STRIDE + seg * 8) * 2),
              &g_Wr[0][(size_t)(j0 + row) * kH + seg * 8]);
    }
    cp_commit();
    cp_wait0();
    __syncthreads();

    // per-lane ldmatrix offsets (m = l>>3 selects the 8x8 sub-matrix)
    const int m    = l >> 3;
    const int arow = r0 + (l & 7) + (m & 1) * 8;
    const int aoff = (arow * SCH_STRIDE + (m >> 1) * 8) * 2;
    const int brow = c0 + (m >> 1) * 8 + (l & 7);
    const int bloff  = (brow * SCH_STRIDE + (m & 1) * 8) * 2;
    const int bhioff = (brow * SBHI_STRIDE + (m & 1) * 8) * 2;

    const uint32_t sBhiU = smem_u32(sBhi);
    uint32_t bufU[kStages];
#pragma unroll
    for (int s = 0; s < kStages; ++s)
        bufU[s] = smem_u32(sBuf + s * BUF_BYTES);

    // xin / epilogue addressing for this thread
    const int rowA = b0 + r0 + (l >> 2);        // rows rowA, rowA+8
    const int col0 = j0 + c0 + 2 * (l & 3);     // nt=0 col pair
    const int col1 = col0 + 8;                  // nt=1 col pair

    for (int t = 0; t < kT; ++t) {
        // ---- prefetch xin accumulator init ----
        const size_t xb0 = ((size_t)rowA * kT + t) * kH;
        const size_t xb8 = ((size_t)(rowA + 8) * kT + t) * kH;
        const float2 x00 = *reinterpret_cast<const float2*>(&g_xin[xb0 + col0]);
        const float2 x01 = *reinterpret_cast<const float2*>(&g_xin[xb0 + col1]);
        const float2 x10 = *reinterpret_cast<const float2*>(&g_xin[xb8 + col0]);
        const float2 x11 = *reinterpret_cast<const float2*>(&g_xin[xb8 + col1]);

        float acc[2][4];
        acc[0][0] = x00.x; acc[0][1] = x00.y; acc[0][2] = x10.x; acc[0][3] = x10.y;
        acc[1][0] = x01.x; acc[1][1] = x01.y; acc[1][2] = x11.x; acc[1][3] = x11.y;

        if (t > 0) {
            // wait until producer tile cc has finished step t-1 (flag >= t).
            // lane 0 of each warp polls; __syncwarp releases the warp.
            auto wait_tile = [&](int cc) {
                if ((tid & 31) == 0) {
                    while (ld_acquire(&flags[cc]) < (unsigned int)t) { }
                }
                __syncwarp();
            };

            // chunk loader: 64-wide K chunk cc into stage buffer bu
            auto load_h_chunk = [&](int cc, uint32_t bu) {
                const int k0 = cc * kChunk;
#pragma unroll
                for (int jj = 0; jj < 2; ++jj) {   // A: 2 planes x 32r x 8s
                    int idx = tid + jj * 256;
                    int plane = idx >> 8, rem = idx & 255;
                    int row = rem >> 3, seg = rem & 7;
                    cpa16(bu + plane * A_PL
                             + (row * SCH_STRIDE + seg * 8) * 2,
                          &g_hb[plane][((size_t)(b0 + row) * kT + (t - 1)) * kH
                                       + k0 + seg * 8]);
                }
#pragma unroll
                for (int jj = 0; jj < 2; ++jj) {   // B_lo: 64 x 8
                    int idx = tid + jj * 256;
                    int row = idx >> 3, seg = idx & 7;
                    cpa16(bu + BLO_OFF
                             + (row * SCH_STRIDE + seg * 8) * 2,
                          &g_Wr[1][(size_t)(j0 + row) * kH + k0 + seg * 8]);
                }
            };

            // ---- prologue: own tile first (no wait), then neighbors ----
#pragma unroll
            for (int s = 0; s < kStages - 1; ++s) {
                const int cc = (jt + s) & (kNCh - 1);
                if (s > 0) wait_tile(cc);          // s==0: own tile, free
                load_h_chunk(cc, bufU[s]);
                cp_commit();
            }

            // ---- steady-state: one sync per chunk, rotated order ----
#pragma unroll 1
            for (int i = 0; i < kNCh; ++i) {
                cp_wait2();          // stage i landed (2 groups may pend)
                __syncthreads();     // cross-thread visibility of stage i

                const int cc = (jt + i) & (kNCh - 1);
                const uint32_t bu   = bufU[i & (kStages - 1)];
                const uint32_t aHiB = bu + aoff;
                const uint32_t aLoB = bu + A_PL + aoff;
                const uint32_t bLoB = bu + BLO_OFF + bloff;
                const uint32_t bHiB = sBhiU + bhioff + (cc * kChunk) * 2;

                // fragment-pipelined MMA loop (4 k16 slices per chunk)
                uint32_t Ah[2][4], Al[2][4], Bh[2][4], Bl[2][4];
                ldm4(Ah[0], aHiB);
                ldm4(Al[0], aLoB);
                ldm4(Bh[0], bHiB);
                ldm4(Bl[0], bLoB);
#pragma unroll
                for (int kk = 0; kk < 4; ++kk) {
                    const int cur = kk & 1;
                    const int nxt = cur ^ 1;
                    if (kk < 3) {
                        ldm4(Ah[nxt], aHiB + (kk + 1) * 32);
                        ldm4(Al[nxt], aLoB + (kk + 1) * 32);
                        ldm4(Bh[nxt], bHiB + (kk + 1) * 32);
                        ldm4(Bl[nxt], bLoB + (kk + 1) * 32);
                    }
                    mma16816(acc[0], Ah[cur], Bh[cur][0], Bh[cur][1]);
                    mma16816(acc[1], Ah[cur], Bh[cur][2], Bh[cur][3]);
                    mma16816(acc[0], Ah[cur], Bl[cur][0], Bl[cur][1]);
                    mma16816(acc[1], Ah[cur], Bl[cur][2], Bl[cur][3]);
                    mma16816(acc[0], Al[cur], Bh[cur][0], Bh[cur][1]);
                    mma16816(acc[1], Al[cur], Bh[cur][2], Bh[cur][3]);
                }

                // issue stage i+3 (flag-gated; buffer reuse safe: all threads
                // passed this iteration's sync, i.e. finished chunk i-1).
                if (i + kStages - 1 < kNCh) {
                    const int cf = (jt + i + kStages - 1) & (kNCh - 1);
                    wait_tile(cf);
                    load_h_chunk(cf, bufU[(i + kStages - 1) & (kStages - 1)]);
                }
                cp_commit();   // empty group in tail keeps wait counting
            }
        }

        // ---- epilogue: relu, fp32 hid + bf16 hi/lo planes ----
#pragma unroll
        for (int nt = 0; nt < 2; ++nt) {
            const int col = (nt == 0) ? col0 : col1;
#pragma unroll
            for (int half = 0; half < 2; ++half) {
                float v0 = fmaxf(acc[nt][2 * half + 0], 0.0f);
                float v1 = fmaxf(acc[nt][2 * half + 1], 0.0f);
                const int row = rowA + half * 8;
                const size_t o = ((size_t)row * kT + t) * kH + col;
                float2 fv; fv.x = v0; fv.y = v1;
                *reinterpret_cast<float2*>(hid + o) = fv;

                __nv_bfloat16 h0, l0, h1, l1;
                split_bf16(v0, h0, l0);
                split_bf16(v1, h1, l1);
                __nv_bfloat162 ph; ph.x = h0; ph.y = h1;
                __nv_bfloat162 pl; pl.x = l0; pl.y = l1;
                *reinterpret_cast<__nv_bfloat162*>(&g_hb[0][o]) = ph;
                *reinterpret_cast<__nv_bfloat162*>(&g_hb[1][o]) = pl;
            }
        }

        // order all threads' g_hb stores before the release-arrive,
        // then publish: this tile has completed step t (flag -> t+1).
        __syncthreads();
        if (tid == 0) barrier_arrive(&flags[jt]);
    }
}

// ---------------------------------------------------------------------------
// Tensorized output projection + softmax (unchanged; ~302 us).
// ---------------------------------------------------------------------------
__global__ __launch_bounds__(256, 1)
void rnn_output_tc(const float* __restrict__ b_out,
                   float* __restrict__ outs)
{
    extern __shared__ char smem[];
    const int tid = threadIdx.x;
    const int w   = tid >> 5;
    const int l   = tid & 31;
    const int m   = l >> 3;
    const size_t r0g = (size_t)blockIdx.x * 128;

    const int aoff = ((w * 16 + (l & 7) + (m & 1) * 8) * GST + (m >> 1) * 8) * 2;
    const int boff = (((m >> 1) * 8 + (l & 7)) * GST + (m & 1) * 8) * 2;
    const uint32_t bufU[2] = { smem_u32(smem), smem_u32(smem + GBUF) };

    float acc[16][4];
#pragma unroll
    for (int j = 0; j < 16; ++j) {
        const int col = j * 8 + 2 * (l & 3);
        float bv0 = b_out[col], bv1 = b_out[col + 1];
        acc[j][0] = bv0; acc[j][1] = bv1; acc[j][2] = bv0; acc[j][3] = bv1;
    }

    auto load_chunk = [&](int c, uint32_t bu) {
        const int k0 = c * 64;
#pragma unroll
        for (int jj = 0; jj < 8; ++jj) {
            int idx = tid + jj * 256;
            int plane = idx >> 10, rem = idx & 1023;
            int row = rem >> 3, seg = rem & 7;
            cpa16(bu + plane * GPA + (row * GST + seg * 8) * 2,
                  &g_hb[plane][(r0g + row) * kH + k0 + seg * 8]);
        }
#pragma unroll
        for (int jj = 0; jj < 8; ++jj) {
            int idx = tid + jj * 256;
            int plane = idx >> 10, rem = idx & 1023;
            int row = rem >> 3, seg = rem & 7;
            cpa16(bu + 2 * GPA + plane * GPA + (row * GST + seg * 8) * 2,
                  &g_Wout[plane][(size_t)row * kH + k0 + seg * 8]);
        }
    };

    load_chunk(0, bufU[0]);
    cp_commit();

#pragma unroll 1
    for (int c = 0; c < 16; ++c) {
        if (c < 15) {
            load_chunk(c + 1, bufU[(c + 1) & 1]);
            cp_commit();
            cp_wait1();
        } else {
            cp_wait0();
        }
        __syncthreads();

        const uint32_t bu  = bufU[c & 1];
        const uint32_t aHi = bu + aoff;
        const uint32_t aLo = bu + GPA + aoff;
        const uint32_t bHi = bu + 2 * GPA + boff;
        const uint32_t bLo = bu + 3 * GPA + boff;

#pragma unroll
        for (int kk = 0; kk < 4; ++kk) {
            uint32_t Ah[4], Al[4];
            ldm4(Ah, aHi + kk * 32);
            ldm4(Al, aLo + kk * 32);
#pragma unroll
            for (int nf = 0; nf < 8; ++nf) {
                uint32_t Bh[4], Bl[4];
                ldm4(Bh, bHi + nf * (16 * GST * 2) + kk * 32);
                ldm4(Bl, bLo + nf * (16 * GST * 2) + kk * 32);
                mma16816(acc[2 * nf],     Ah, Bh[0], Bh[1]);
                mma16816(acc[2 * nf + 1], Ah, Bh[2], Bh[3]);
                mma16816(acc[2 * nf],     Ah, Bl[0], Bl[1]);
                mma16816(acc[2 * nf + 1], Ah, Bl[2], Bl[3]);
                mma16816(acc[2 * nf],     Al, Bh[0], Bh[1]);
                mma16816(acc[2 * nf + 1], Al, Bh[2], Bh[3]);
            }
        }
        __syncthreads();
    }

#pragma unroll
    for (int half = 0; half < 2; ++half) {
        float mx = -1e30f;
#pragma unroll
        for (int j = 0; j < 16; ++j) {
            mx = fmaxf(mx, acc[j][2 * half + 0]);
            mx = fmaxf(mx, acc[j][2 * half + 1]);
        }
        mx = fmaxf(mx, __shfl_xor_sync(0xffffffffu, mx, 1));
        mx = fmaxf(mx, __shfl_xor_sync(0xffffffffu, mx, 2));

        float e[32], s = 0.0f;
#pragma unroll
        for (int j = 0; j < 16; ++j) {
            e[2 * j]     = expf(acc[j][2 * half + 0] - mx);
            e[2 * j + 1] = expf(acc[j][2 * half + 1] - mx);
            s += e[2 * j] + e[2 * j + 1];
        }
        s += __shfl_xor_sync(0xffffffffu, s, 1);
        s += __shfl_xor_sync(0xffffffffu, s, 2);
        const float inv = 1.0f / s;

        const size_t row = r0g + w * 16 + (l >> 2) + half * 8;
#pragma unroll
        for (int j = 0; j < 16; ++j) {
            float2 o;
            o.x = e[2 * j] * inv;
            o.y = e[2 * j + 1] * inv;
            *reinterpret_cast<float2*>(
                outs + row * kO + j * 8 + 2 * (l & 3)) = o;
        }
    }
}

// ---------------------------------------------------------------------------
// d_in order: x, W_in, b_in, Wrec, W_out, b_out
// d_out: hiddens [B,T,H] fp32 followed by outs [B,T,O] fp32
// ---------------------------------------------------------------------------
extern "C" void kernel_launch(void* const* d_in, const int* in_sizes, int n_in,
                              void* d_out, int out_size) {
    (void)in_sizes; (void)n_in; (void)out_size;
    const float* x     = (const float*)d_in[0];
    const float* W_in  = (const float*)d_in[1];
    const float* b_in  = (const float*)d_in[2];
    const float* Wrec  = (const float*)d_in[3];
    const float* W_out = (const float*)d_in[4];
    const float* b_out = (const float*)d_in[5];

    float* hid  = (float*)d_out;                 // [B,T,H]
    float* outs = hid + (size_t)kB * kT * kH;    // [B,T,O]

    cudaFuncSetAttribute(rnn_rec_tc,
                         cudaFuncAttributeMaxDynamicSharedMemorySize,
                         SMEM_TOTAL);
    cudaFuncSetAttribute(xin_gemm_tc,
                         cudaFuncAttributeMaxDynamicSharedMemorySize, GSMEM);
    cudaFuncSetAttribute(rnn_output_tc,
                         cudaFuncAttributeMaxDynamicSharedMemorySize, GSMEM);

    convert_w_kernel<<<1024, 256>>>(Wrec, W_in, W_out);   // also resets flags
    convert_x_kernel<<<4096, 256>>>(x);
    xin_gemm_tc<<<8192, 256, GSMEM>>>(b_in);
    rnn_rec_tc<<<kGroups * kTilesPerGroup, 256, SMEM_TOTAL>>>(hid);
    rnn_output_tc<<<(kB * kT) / 128, 256, GSMEM>>>(b_out, outs);
}

// round 16
// speedup vs baseline: 1.6126x; 1.6126x over previous
#include <cuda_runtime.h>
#include <cuda_bf16.h>
#include <cuda_fp16.h>
#include <math.h>
#include <stdint.h>

// Problem constants (nondecayRNN: B=256, T=512, I=128, H=1024, O=128)
namespace {
constexpr int kB = 256;
constexpr int kT = 512;
constexpr int kI = 128;
constexpr int kH = 1024;
constexpr int kO = 128;

constexpr int kGroups        = 8;                 // independent batch groups
constexpr int kBc            = kB / kGroups;      // 32 batch rows / group
constexpr int kTilesPerGroup = 16;                // N-tiles of 64 over H
constexpr int kTN            = kH / kTilesPerGroup; // 64

constexpr int kChunk  = 128;       // K chunk (8 chunks cover K=1024)

// Recurrence SMEM layout (bytes)
constexpr int SBHI_STRIDE = 1032;  // fp16 elems per n-row, padded (1024+8)
constexpr int SCH_STRIDE  = 136;   // fp16 elems per row in chunk bufs (128+8)
constexpr int A_BYTES   = 32 * SCH_STRIDE * 2;        // 8704 (single A plane)
constexpr int BLO_OFF   = A_BYTES;                    // B_lo after A
constexpr int BLO_BYTES = 64 * SCH_STRIDE * 2;        // 17408
constexpr int BUF_BYTES = A_BYTES + BLO_BYTES;        // 26112
constexpr int BHI_BYTES = 64 * SBHI_STRIDE * 2;       // 132096 persistent
constexpr int SMEM_TOTAL = BHI_BYTES + 2 * BUF_BYTES; // 184320

// xin GEMM config (bf16 3-pass, unchanged): CTA 128x128, padded stride 72
constexpr int GST   = 72;
constexpr int GPA   = 128 * GST * 2;       // 18432 B per plane tile
constexpr int GBUF  = 4 * GPA;             // Ahi|Alo|Bhi|Blo = 73728
constexpr int GSMEM = 2 * GBUF;            // 147456

// output GEMM config (fp16 2-pass): A(1 plane) + Bhi + Blo = 3 planes
constexpr int OBUF  = 3 * GPA;             // 55296
constexpr int OSMEM = 2 * OBUF;            // 110592
}

// ---------------------------------------------------------------------------
// Device scratch (static __device__ arrays — no runtime allocation)
// ---------------------------------------------------------------------------
__device__ unsigned int   g_count[kGroups];                 // group barriers
__device__ __half         g_Wr[2][kH * kH];                 // Wrec  fp16 [hi/lo]
__device__ __nv_bfloat16  g_Wi[2][kH * kI];                 // W_in  bf16 [hi/lo]
__device__ __half         g_Wout[2][kO * kH];               // W_out fp16 [hi/lo]
__device__ __nv_bfloat16  g_xs[2][(size_t)kB * kT * kI];    // x     bf16 [hi/lo]
__device__ float          g_xin[(size_t)kB * kT * kH];      // xin+b_in (fp32)
__device__ __half         g_hb[(size_t)kB * kT * kH];       // hiddens fp16

// ---------------------------------------------------------------------------
// PTX helpers
// ---------------------------------------------------------------------------
__device__ __forceinline__ uint32_t smem_u32(const void* p) {
    return (uint32_t)__cvta_generic_to_shared(p);
}
__device__ __forceinline__ void cpa16(uint32_t dst, const void* src) {
    asm volatile("cp.async.cg.shared.global [%0], [%1], 16;"
                 :: "r"(dst), "l"(src) : "memory");
}
__device__ __forceinline__ void cp_commit() {
    asm volatile("cp.async.commit_group;" ::: "memory");
}
__device__ __forceinline__ void cp_wait0() {
    asm volatile("cp.async.wait_group 0;" ::: "memory");
}
__device__ __forceinline__ void cp_wait1() {
    asm volatile("cp.async.wait_group 1;" ::: "memory");
}
__device__ __forceinline__ void ldm4(uint32_t* r, uint32_t addr) {
    asm volatile("ldmatrix.sync.aligned.m8n8.x4.shared.b16 {%0,%1,%2,%3}, [%4];"
                 : "=r"(r[0]), "=r"(r[1]), "=r"(r[2]), "=r"(r[3]) : "r"(addr));
}
// bf16 mma (xin kernel)
__device__ __forceinline__ void mma_bf16(float* d, const uint32_t* a,
                                         uint32_t b0, uint32_t b1) {
    asm volatile(
        "mma.sync.aligned.m16n8k16.row.col.f32.bf16.bf16.f32 "
        "{%0,%1,%2,%3}, {%4,%5,%6,%7}, {%8,%9}, {%0,%1,%2,%3};"
        : "+f"(d[0]), "+f"(d[1]), "+f"(d[2]), "+f"(d[3])
        : "r"(a[0]), "r"(a[1]), "r"(a[2]), "r"(a[3]), "r"(b0), "r"(b1));
}
// fp16 mma (recurrence + output)
__device__ __forceinline__ void mma_f16(float* d, const uint32_t* a,
                                        uint32_t b0, uint32_t b1) {
    asm volatile(
        "mma.sync.aligned.m16n8k16.row.col.f32.f16.f16.f32 "
        "{%0,%1,%2,%3}, {%4,%5,%6,%7}, {%8,%9}, {%0,%1,%2,%3};"
        : "+f"(d[0]), "+f"(d[1]), "+f"(d[2]), "+f"(d[3])
        : "r"(a[0]), "r"(a[1]), "r"(a[2]), "r"(a[3]), "r"(b0), "r"(b1));
}
__device__ __forceinline__ void split_bf16(float v, __nv_bfloat16& hi,
                                           __nv_bfloat16& lo) {
    hi = __float2bfloat16(v);
    lo = __float2bfloat16(v - __bfloat162float(hi));
}
__device__ __forceinline__ void split_f16(float v, __half& hi, __half& lo) {
    hi = __float2half_rn(v);
    lo = __float2half_rn(v - __half2float(hi));
}
__device__ __forceinline__ void barrier_arrive(unsigned int* p) {
    asm volatile("red.release.gpu.global.add.u32 [%0], %1;"
                 :: "l"(p), "r"(1u) : "memory");
}
__device__ __forceinline__ unsigned int ld_acquire(const unsigned int* p) {
    unsigned int v;
    asm volatile("ld.acquire.gpu.global.u32 %0, [%1];"
                 : "=r"(v) : "l"(p) : "memory");
    return v;
}

// ---------------------------------------------------------------------------
// Prepass: Wrec/W_out -> fp16 hi/lo planes; W_in -> bf16 hi/lo; reset counters.
// ---------------------------------------------------------------------------
__global__ void convert_w_kernel(const float* __restrict__ Wrec,
                                 const float* __restrict__ W_in,
                                 const float* __restrict__ W_out) {
    if (blockIdx.x == 0 && threadIdx.x < kGroups) g_count[threadIdx.x] = 0u;
    const int stride = gridDim.x * blockDim.x;
    const int base   = blockIdx.x * blockDim.x + threadIdx.x;

    for (int idx = base; idx < kH * kH; idx += stride) {
        __half hi, lo;
        split_f16(Wrec[idx], hi, lo);
        g_Wr[0][idx] = hi;
        g_Wr[1][idx] = lo;
    }
    for (int idx = base; idx < kH * kI; idx += stride) {
        __nv_bfloat16 hi, lo;
        split_bf16(W_in[idx], hi, lo);
        g_Wi[0][idx] = hi;
        g_Wi[1][idx] = lo;
    }
    for (int idx = base; idx < kO * kH; idx += stride) {
        __half hi, lo;
        split_f16(W_out[idx], hi, lo);
        g_Wout[0][idx] = hi;
        g_Wout[1][idx] = lo;
    }
}

// Prepass: split x into bf16 hi/lo planes (same [B][T][I] layout).
__global__ void convert_x_kernel(const float* __restrict__ x) {
    const int n4 = (kB * kT * kI) / 4;
    __nv_bfloat162* xh = reinterpret_cast<__nv_bfloat162*>(g_xs[0]);
    __nv_bfloat162* xl = reinterpret_cast<__nv_bfloat162*>(g_xs[1]);
    for (int i = blockIdx.x * blockDim.x + threadIdx.x; i < n4;
         i += gridDim.x * blockDim.x) {
        float4 v = reinterpret_cast<const float4*>(x)[i];
        float vs[4] = {v.x, v.y, v.z, v.w};
        __nv_bfloat16 hi[4], lo[4];
#pragma unroll
        for (int k = 0; k < 4; ++k) split_bf16(vs[k], hi[k], lo[k]);
        __nv_bfloat162 p;
        p.x = hi[0]; p.y = hi[1]; xh[2 * i]     = p;
        p.x = hi[2]; p.y = hi[3]; xh[2 * i + 1] = p;
        p.x = lo[0]; p.y = lo[1]; xl[2 * i]     = p;
        p.x = lo[2]; p.y = lo[3]; xl[2 * i + 1] = p;
    }
}

// ---------------------------------------------------------------------------
// xin GEMM: g_xin[r, j] = x[r] @ W_in^T[j] + b_in[j] (bf16 3-pass, unchanged).
// ---------------------------------------------------------------------------
__global__ __launch_bounds__(256, 1)
void xin_gemm_tc(const float* __restrict__ b_in)
{
    extern __shared__ char smem[];
    const int tid = threadIdx.x;
    const int w   = tid >> 5;
    const int l   = tid & 31;
    const int m   = l >> 3;
    const int cb  = blockIdx.x & 7;
    const size_t r0g = (size_t)(blockIdx.x >> 3) * 128;
    const int j0  = cb * 128;

    const int aoff = ((w * 16 + (l & 7) + (m & 1) * 8) * GST + (m >> 1) * 8) * 2;
    const int boff = (((m >> 1) * 8 + (l & 7)) * GST + (m & 1) * 8) * 2;
    const uint32_t bufU[2] = { smem_u32(smem), smem_u32(smem + GBUF) };

    float acc[16][4];
#pragma unroll
    for (int j = 0; j < 16; ++j)
#pragma unroll
        for (int v = 0; v < 4; ++v) acc[j][v] = 0.0f;

    auto load_chunk = [&](int c, uint32_t bu) {
        const int k0 = c * 64;
#pragma unroll
        for (int jj = 0; jj < 8; ++jj) {
            int idx = tid + jj * 256;
            int plane = idx >> 10, rem = idx & 1023;
            int row = rem >> 3, seg = rem & 7;
            cpa16(bu + plane * GPA + (row * GST + seg * 8) * 2,
                  &g_xs[plane][(r0g + row) * kI + k0 + seg * 8]);
        }
#pragma unroll
        for (int jj = 0; jj < 8; ++jj) {
            int idx = tid + jj * 256;
            int plane = idx >> 10, rem = idx & 1023;
            int row = rem >> 3, seg = rem & 7;
            cpa16(bu + 2 * GPA + plane * GPA + (row * GST + seg * 8) * 2,
                  &g_Wi[plane][(size_t)(j0 + row) * kI + k0 + seg * 8]);
        }
    };

    load_chunk(0, bufU[0]);
    cp_commit();
    load_chunk(1, bufU[1]);
    cp_commit();

#pragma unroll 1
    for (int c = 0; c < 2; ++c) {
        if (c == 0) cp_wait1(); else cp_wait0();
        __syncthreads();
        const uint32_t bu  = bufU[c];
        const uint32_t aHi = bu + aoff;
        const uint32_t aLo = bu + GPA + aoff;
        const uint32_t bHi = bu + 2 * GPA + boff;
        const uint32_t bLo = bu + 3 * GPA + boff;
#pragma unroll
        for (int kk = 0; kk < 4; ++kk) {
            uint32_t Ah[4], Al[4];
            ldm4(Ah, aHi + kk * 32);
            ldm4(Al, aLo + kk * 32);
#pragma unroll
            for (int nf = 0; nf < 8; ++nf) {
                uint32_t Bh[4], Bl[4];
                ldm4(Bh, bHi + nf * (16 * GST * 2) + kk * 32);
                ldm4(Bl, bLo + nf * (16 * GST * 2) + kk * 32);
                mma_bf16(acc[2 * nf],     Ah, Bh[0], Bh[1]);
                mma_bf16(acc[2 * nf + 1], Ah, Bh[2], Bh[3]);
                mma_bf16(acc[2 * nf],     Ah, Bl[0], Bl[1]);
                mma_bf16(acc[2 * nf + 1], Ah, Bl[2], Bl[3]);
                mma_bf16(acc[2 * nf],     Al, Bh[0], Bh[1]);
                mma_bf16(acc[2 * nf + 1], Al, Bh[2], Bh[3]);
            }
        }
    }

#pragma unroll
    for (int half = 0; half < 2; ++half) {
        const size_t row = r0g + w * 16 + (l >> 2) + half * 8;
#pragma unroll
        for (int j = 0; j < 16; ++j) {
            const int col = j * 8 + 2 * (l & 3);
            float2 o;
            o.x = acc[j][2 * half + 0] + b_in[j0 + col];
            o.y = acc[j][2 * half + 1] + b_in[j0 + col + 1];
            *reinterpret_cast<float2*>(&g_xin[row * kH + j0 + col]) = o;
        }
    }
}

// ---------------------------------------------------------------------------
// fp16 2-pass tensor-core recurrence (R14 skeleton: monolithic group barrier,
// 8 chunks of 128, 2-stage cp.async, fragment double-buffering).
//   h stored as SINGLE fp16 plane (A-lo dropped); Wrec as fp16 hi+lo.
//   D += A*Bh + A*Bl   (16 MMAs + 24 ldm4 per chunk per warp, was 24+32).
// Grid: 128 CTAs = 8 groups x 16 N-tiles, 256 thr (8 warps = 2M x 4N).
// ---------------------------------------------------------------------------
__global__ __launch_bounds__(256, 1)
void rnn_rec_tc(float* __restrict__ hid)   // [B, T, H] fp32 output
{
    extern __shared__ char smem[];
    char* sBhi  = smem;                    // persistent Wrec_hi [64][1032]
    char* sBuf0 = smem + BHI_BYTES;
    char* sBuf1 = sBuf0 + BUF_BYTES;

    const int tid = threadIdx.x;
    const int g   = blockIdx.x / kTilesPerGroup;
    const int jt  = blockIdx.x % kTilesPerGroup;
    const int j0  = jt * kTN;
    const int b0  = g * kBc;
    const int w   = tid >> 5;
    const int l   = tid & 31;
    const int r0  = (w >> 2) * 16;   // A-row base within 32-row tile
    const int c0  = (w & 3) * 16;    // n base within 64-col tile

    // ---- persistent Wrec_hi slice load: 64 rows x 128 segs of 8 ----
#pragma unroll
    for (int j = 0; j < 32; ++j) {
        int idx = tid + j * 256;
        int row = idx >> 7, seg = idx & 127;
        cpa16(smem_u32(sBhi + (row * SBHI_STRIDE + seg * 8) * 2),
              &g_Wr[0][(size_t)(j0 + row) * kH + seg * 8]);
    }
    cp_commit();
    cp_wait0();
    __syncthreads();

    // per-lane ldmatrix offsets (m = l>>3 selects the 8x8 sub-matrix)
    const int m    = l >> 3;
    const int arow = r0 + (l & 7) + (m & 1) * 8;
    const int aoff = (arow * SCH_STRIDE + (m >> 1) * 8) * 2;
    const int brow = c0 + (m >> 1) * 8 + (l & 7);
    const int bloff  = (brow * SCH_STRIDE + (m & 1) * 8) * 2;
    const int bhioff = (brow * SBHI_STRIDE + (m & 1) * 8) * 2;

    const uint32_t sBhiU   = smem_u32(sBhi);
    const uint32_t bufU[2] = { smem_u32(sBuf0), smem_u32(sBuf1) };

    // xin / epilogue addressing for this thread
    const int rowA = b0 + r0 + (l >> 2);        // rows rowA, rowA+8
    const int col0 = j0 + c0 + 2 * (l & 3);     // nt=0 col pair
    const int col1 = col0 + 8;                  // nt=1 col pair

    for (int t = 0; t < kT; ++t) {
        // ---- prefetch xin accumulator init (independent of barrier) ----
        const size_t xb0 = ((size_t)rowA * kT + t) * kH;
        const size_t xb8 = ((size_t)(rowA + 8) * kT + t) * kH;
        const float2 x00 = *reinterpret_cast<const float2*>(&g_xin[xb0 + col0]);
        const float2 x01 = *reinterpret_cast<const float2*>(&g_xin[xb0 + col1]);
        const float2 x10 = *reinterpret_cast<const float2*>(&g_xin[xb8 + col0]);
        const float2 x11 = *reinterpret_cast<const float2*>(&g_xin[xb8 + col1]);

        float acc[2][4];
        acc[0][0] = x00.x; acc[0][1] = x00.y; acc[0][2] = x10.x; acc[0][3] = x10.y;
        acc[1][0] = x01.x; acc[1][1] = x01.y; acc[1][2] = x11.x; acc[1][3] = x11.y;

        if (t > 0) {
            // ---- wait for h_{t-1} (group barrier, acquire) ----
            if (tid == 0) {
                const unsigned int target =
                    (unsigned int)(kTilesPerGroup * t);
                while (ld_acquire(&g_count[g]) < target) { }
            }
            __syncthreads();

            // ---- 8 h-chunks, 2-buffer cp.async pipeline ----
            auto load_h_chunk = [&](int c, uint32_t bu) {
#pragma unroll
                for (int jj = 0; jj < 2; ++jj) {   // A: 1 plane x 32r x 16s
                    int idx = tid + jj * 256;
                    int row = idx >> 4, seg = idx & 15;
                    cpa16(bu + (row * SCH_STRIDE + seg * 8) * 2,
                          &g_hb[((size_t)(b0 + row) * kT + (t - 1)) * kH
                                + c * kChunk + seg * 8]);
                }
#pragma unroll
                for (int jj = 0; jj < 4; ++jj) {   // B_lo: 64 x 16
                    int idx = tid + jj * 256;
                    int row = idx >> 4, seg = idx & 15;
                    cpa16(bu + BLO_OFF
                             + (row * SCH_STRIDE + seg * 8) * 2,
                          &g_Wr[1][(size_t)(j0 + row) * kH
                                   + c * kChunk + seg * 8]);
                }
            };

            load_h_chunk(0, bufU[0]);
            cp_commit();
#pragma unroll 1
            for (int c = 0; c < 8; ++c) {
                if (c < 7) {
                    load_h_chunk(c + 1, bufU[(c + 1) & 1]);
                    cp_commit();
                    cp_wait1();
                } else {
                    cp_wait0();
                }
                __syncthreads();

                const uint32_t bu   = bufU[c & 1];
                const uint32_t aB   = bu + aoff;
                const uint32_t bLoB = bu + BLO_OFF + bloff;
                const uint32_t bHiB = sBhiU + bhioff + (c * kChunk) * 2;

                // fragment-pipelined 2-pass MMA loop
                uint32_t Ah[2][4], Bh[2][4], Bl[2][4];
                ldm4(Ah[0], aB);
                ldm4(Bh[0], bHiB);
                ldm4(Bl[0], bLoB);
#pragma unroll
                for (int kk = 0; kk < 8; ++kk) {
                    const int cur = kk & 1;
                    const int nxt = cur ^ 1;
                    if (kk < 7) {
                        ldm4(Ah[nxt], aB + (kk + 1) * 32);
                        ldm4(Bh[nxt], bHiB + (kk + 1) * 32);
                        ldm4(Bl[nxt], bLoB + (kk + 1) * 32);
                    }
                    mma_f16(acc[0], Ah[cur], Bh[cur][0], Bh[cur][1]);
                    mma_f16(acc[1], Ah[cur], Bh[cur][2], Bh[cur][3]);
                    mma_f16(acc[0], Ah[cur], Bl[cur][0], Bl[cur][1]);
                    mma_f16(acc[1], Ah[cur], Bl[cur][2], Bl[cur][3]);
                }
                __syncthreads();   // protect buf before refill
            }
        }

        // ---- epilogue: relu, fp32 hid + single fp16 plane ----
#pragma unroll
        for (int nt = 0; nt < 2; ++nt) {
            const int col = (nt == 0) ? col0 : col1;
#pragma unroll
            for (int half = 0; half < 2; ++half) {
                float v0 = fmaxf(acc[nt][2 * half + 0], 0.0f);
                float v1 = fmaxf(acc[nt][2 * half + 1], 0.0f);
                const int row = rowA + half * 8;
                const size_t o = ((size_t)row * kT + t) * kH + col;
                float2 fv; fv.x = v0; fv.y = v1;
                *reinterpret_cast<float2*>(hid + o) = fv;

                __half2 hp;
                hp.x = __float2half_rn(v0);
                hp.y = __float2half_rn(v1);
                *reinterpret_cast<__half2*>(&g_hb[o]) = hp;
            }
        }

        // order all threads' g_hb stores before the release-arrive
        __syncthreads();
        if (tid == 0) barrier_arrive(&g_count[g]);
    }
}

// ---------------------------------------------------------------------------
// fp16 2-pass output projection + softmax: A = fp16 h (single plane),
// B = W_out fp16 hi+lo. Grid 1024 x 256 thr, CTA = 128 rows x 128 O-cols.
// ---------------------------------------------------------------------------
__global__ __launch_bounds__(256, 1)
void rnn_output_tc(const float* __restrict__ b_out,
                   float* __restrict__ outs)
{
    extern __shared__ char smem[];
    const int tid = threadIdx.x;
    const int w   = tid >> 5;
    const int l   = tid & 31;
    const int m   = l >> 3;
    const size_t r0g = (size_t)blockIdx.x * 128;

    const int aoff = ((w * 16 + (l & 7) + (m & 1) * 8) * GST + (m >> 1) * 8) * 2;
    const int boff = (((m >> 1) * 8 + (l & 7)) * GST + (m & 1) * 8) * 2;
    const uint32_t bufU[2] = { smem_u32(smem), smem_u32(smem + OBUF) };

    float acc[16][4];
#pragma unroll
    for (int j = 0; j < 16; ++j) {
        const int col = j * 8 + 2 * (l & 3);
        float bv0 = b_out[col], bv1 = b_out[col + 1];
        acc[j][0] = bv0; acc[j][1] = bv1; acc[j][2] = bv0; acc[j][3] = bv1;
    }

    auto load_chunk = [&](int c, uint32_t bu) {
        const int k0 = c * 64;
#pragma unroll
        for (int jj = 0; jj < 4; ++jj) {     // A: 1 plane x 128 rows x 8 segs
            int idx = tid + jj * 256;
            int row = idx >> 3, seg = idx & 7;
            cpa16(bu + (row * GST + seg * 8) * 2,
                  &g_hb[(r0g + row) * kH + k0 + seg * 8]);
        }
#pragma unroll
        for (int jj = 0; jj < 8; ++jj) {     // B: 2 planes x 128 n x 8 segs
            int idx = tid + jj * 256;
            int plane = idx >> 10, rem = idx & 1023;
            int row = rem >> 3, seg = rem & 7;
            cpa16(bu + GPA + plane * GPA + (row * GST + seg * 8) * 2,
                  &g_Wout[plane][(size_t)row * kH + k0 + seg * 8]);
        }
    };

    load_chunk(0, bufU[0]);
    cp_commit();

#pragma unroll 1
    for (int c = 0; c < 16; ++c) {
        if (c < 15) {
            load_chunk(c + 1, bufU[(c + 1) & 1]);
            cp_commit();
            cp_wait1();
        } else {
            cp_wait0();
        }
        __syncthreads();

        const uint32_t bu  = bufU[c & 1];
        const uint32_t aB  = bu + aoff;
        const uint32_t bHi = bu + GPA + boff;
        const uint32_t bLo = bu + 2 * GPA + boff;

#pragma unroll
        for (int kk = 0; kk < 4; ++kk) {
            uint32_t Ah[4];
            ldm4(Ah, aB + kk * 32);
#pragma unroll
            for (int nf = 0; nf < 8; ++nf) {
                uint32_t Bh[4], Bl[4];
                ldm4(Bh, bHi + nf * (16 * GST * 2) + kk * 32);
                ldm4(Bl, bLo + nf * (16 * GST * 2) + kk * 32);
                mma_f16(acc[2 * nf],     Ah, Bh[0], Bh[1]);
                mma_f16(acc[2 * nf + 1], Ah, Bh[2], Bh[3]);
                mma_f16(acc[2 * nf],     Ah, Bl[0], Bl[1]);
                mma_f16(acc[2 * nf + 1], Ah, Bl[2], Bl[3]);
            }
        }
        __syncthreads();
    }

#pragma unroll
    for (int half = 0; half < 2; ++half) {
        float mx = -1e30f;
#pragma unroll
        for (int j = 0; j < 16; ++j) {
            mx = fmaxf(mx, acc[j][2 * half + 0]);
            mx = fmaxf(mx, acc[j][2 * half + 1]);
        }
        mx = fmaxf(mx, __shfl_xor_sync(0xffffffffu, mx, 1));
        mx = fmaxf(mx, __shfl_xor_sync(0xffffffffu, mx, 2));

        float e[32], s = 0.0f;
#pragma unroll
        for (int j = 0; j < 16; ++j) {
            e[2 * j]     = expf(acc[j][2 * half + 0] - mx);
            e[2 * j + 1] = expf(acc[j][2 * half + 1] - mx);
            s += e[2 * j] + e[2 * j + 1];
        }
        s += __shfl_xor_sync(0xffffffffu, s, 1);
        s += __shfl_xor_sync(0xffffffffu, s, 2);
        const float inv = 1.0f / s;

        const size_t row = r0g + w * 16 + (l >> 2) + half * 8;
#pragma unroll
        for (int j = 0; j < 16; ++j) {
            float2 o;
            o.x = e[2 * j] * inv;
            o.y = e[2 * j + 1] * inv;
            *reinterpret_cast<float2*>(
                outs + row * kO + j * 8 + 2 * (l & 3)) = o;
        }
    }
}

// ---------------------------------------------------------------------------
// d_in order: x, W_in, b_in, Wrec, W_out, b_out
// d_out: hiddens [B,T,H] fp32 followed by outs [B,T,O] fp32
// ---------------------------------------------------------------------------
extern "C" void kernel_launch(void* const* d_in, const int* in_sizes, int n_in,
                              void* d_out, int out_size) {
    (void)in_sizes; (void)n_in; (void)out_size;
    const float* x     = (const float*)d_in[0];
    const float* W_in  = (const float*)d_in[1];
    const float* b_in  = (const float*)d_in[2];
    const float* Wrec  = (const float*)d_in[3];
    const float* W_out = (const float*)d_in[4];
    const float* b_out = (const float*)d_in[5];

    float* hid  = (float*)d_out;                 // [B,T,H]
    float* outs = hid + (size_t)kB * kT * kH;    // [B,T,O]

    cudaFuncSetAttribute(rnn_rec_tc,
                         cudaFuncAttributeMaxDynamicSharedMemorySize,
                         SMEM_TOTAL);
    cudaFuncSetAttribute(xin_gemm_tc,
                         cudaFuncAttributeMaxDynamicSharedMemorySize, GSMEM);
    cudaFuncSetAttribute(rnn_output_tc,
                         cudaFuncAttributeMaxDynamicSharedMemorySize, OSMEM);

    convert_w_kernel<<<1024, 256>>>(Wrec, W_in, W_out);   // also resets counters
    convert_x_kernel<<<4096, 256>>>(x);
    xin_gemm_tc<<<8192, 256, GSMEM>>>(b_in);
    rnn_rec_tc<<<kGroups * kTilesPerGroup, 256, SMEM_TOTAL>>>(hid);
    rnn_output_tc<<<(kB * kT) / 128, 256, OSMEM>>>(b_out, outs);
}

// round 17
// speedup vs baseline: 2.2531x; 1.3972x over previous
#include <cuda_runtime.h>
#include <cuda_bf16.h>
#include <cuda_fp16.h>
#include <math.h>
#include <stdint.h>

// Problem constants (nondecayRNN: B=256, T=512, I=128, H=1024, O=128)
namespace {
constexpr int kB = 256;
constexpr int kT = 512;
constexpr int kI = 128;
constexpr int kH = 1024;
constexpr int kO = 128;

constexpr int kGroups        = 8;                 // independent batch groups
constexpr int kBc            = kB / kGroups;      // 32 batch rows / group
constexpr int kTilesPerGroup = 16;                // N-tiles of 64 over H
constexpr int kTN            = kH / kTilesPerGroup; // 64

constexpr int kChunk  = 128;       // K chunk (8 chunks cover K=1024)

// Recurrence SMEM layout (bytes) — 1-pass: chunk buffer holds A only
constexpr int SBHI_STRIDE = 1032;  // fp16 elems per n-row, padded (1024+8)
constexpr int SCH_STRIDE  = 136;   // fp16 elems per row in chunk bufs (128+8)
constexpr int A_BYTES   = 32 * SCH_STRIDE * 2;        // 8704 (single A plane)
constexpr int BUF_BYTES = A_BYTES;                    // 8704
constexpr int BHI_BYTES = 64 * SBHI_STRIDE * 2;       // 132096 persistent
constexpr int SMEM_TOTAL = BHI_BYTES + 2 * BUF_BYTES; // 149504

// xin GEMM config (bf16 3-pass, unchanged): CTA 128x128, padded stride 72
constexpr int GST   = 72;
constexpr int GPA   = 128 * GST * 2;       // 18432 B per plane tile
constexpr int GBUF  = 4 * GPA;             // Ahi|Alo|Bhi|Blo = 73728
constexpr int GSMEM = 2 * GBUF;            // 147456

// output GEMM config (fp16 2-pass): A(1 plane) + Bhi + Blo = 3 planes
constexpr int OBUF  = 3 * GPA;             // 55296
constexpr int OSMEM = 2 * OBUF;            // 110592
}

// ---------------------------------------------------------------------------
// Device scratch (static __device__ arrays — no runtime allocation)
// ---------------------------------------------------------------------------
__device__ unsigned int   g_count[kGroups];                 // group barriers
__device__ __half         g_Wr[kH * kH];                    // Wrec  fp16 (hi only)
__device__ __nv_bfloat16  g_Wi[2][kH * kI];                 // W_in  bf16 [hi/lo]
__device__ __half         g_Wout[2][kO * kH];               // W_out fp16 [hi/lo]
__device__ __nv_bfloat16  g_xs[2][(size_t)kB * kT * kI];    // x     bf16 [hi/lo]
__device__ float          g_xin[(size_t)kB * kT * kH];      // xin+b_in (fp32)
__device__ __half         g_hb[(size_t)kB * kT * kH];       // hiddens fp16

// ---------------------------------------------------------------------------
// PTX helpers
// ---------------------------------------------------------------------------
__device__ __forceinline__ uint32_t smem_u32(const void* p) {
    return (uint32_t)__cvta_generic_to_shared(p);
}
__device__ __forceinline__ void cpa16(uint32_t dst, const void* src) {
    asm volatile("cp.async.cg.shared.global [%0], [%1], 16;"
                 :: "r"(dst), "l"(src) : "memory");
}
__device__ __forceinline__ void cp_commit() {
    asm volatile("cp.async.commit_group;" ::: "memory");
}
__device__ __forceinline__ void cp_wait0() {
    asm volatile("cp.async.wait_group 0;" ::: "memory");
}
__device__ __forceinline__ void cp_wait1() {
    asm volatile("cp.async.wait_group 1;" ::: "memory");
}
__device__ __forceinline__ void ldm4(uint32_t* r, uint32_t addr) {
    asm volatile("ldmatrix.sync.aligned.m8n8.x4.shared.b16 {%0,%1,%2,%3}, [%4];"
                 : "=r"(r[0]), "=r"(r[1]), "=r"(r[2]), "=r"(r[3]) : "r"(addr));
}
// bf16 mma (xin kernel)
__device__ __forceinline__ void mma_bf16(float* d, const uint32_t* a,
                                         uint32_t b0, uint32_t b1) {
    asm volatile(
        "mma.sync.aligned.m16n8k16.row.col.f32.bf16.bf16.f32 "
        "{%0,%1,%2,%3}, {%4,%5,%6,%7}, {%8,%9}, {%0,%1,%2,%3};"
        : "+f"(d[0]), "+f"(d[1]), "+f"(d[2]), "+f"(d[3])
        : "r"(a[0]), "r"(a[1]), "r"(a[2]), "r"(a[3]), "r"(b0), "r"(b1));
}
// fp16 mma (recurrence + output)
__device__ __forceinline__ void mma_f16(float* d, const uint32_t* a,
                                        uint32_t b0, uint32_t b1) {
    asm volatile(
        "mma.sync.aligned.m16n8k16.row.col.f32.f16.f16.f32 "
        "{%0,%1,%2,%3}, {%4,%5,%6,%7}, {%8,%9}, {%0,%1,%2,%3};"
        : "+f"(d[0]), "+f"(d[1]), "+f"(d[2]), "+f"(d[3])
        : "r"(a[0]), "r"(a[1]), "r"(a[2]), "r"(a[3]), "r"(b0), "r"(b1));
}
__device__ __forceinline__ void split_bf16(float v, __nv_bfloat16& hi,
                                           __nv_bfloat16& lo) {
    hi = __float2bfloat16(v);
    lo = __float2bfloat16(v - __bfloat162float(hi));
}
__device__ __forceinline__ void split_f16(float v, __half& hi, __half& lo) {
    hi = __float2half_rn(v);
    lo = __float2half_rn(v - __half2float(hi));
}
__device__ __forceinline__ void barrier_arrive(unsigned int* p) {
    asm volatile("red.release.gpu.global.add.u32 [%0], %1;"
                 :: "l"(p), "r"(1u) : "memory");
}
__device__ __forceinline__ unsigned int ld_acquire(const unsigned int* p) {
    unsigned int v;
    asm volatile("ld.acquire.gpu.global.u32 %0, [%1];"
                 : "=r"(v) : "l"(p) : "memory");
    return v;
}

// ---------------------------------------------------------------------------
// Prepass: Wrec -> fp16 (hi only); W_out -> fp16 hi/lo; W_in -> bf16 hi/lo.
// Also resets barrier counters (graph-replay deterministic).
// ---------------------------------------------------------------------------
__global__ void convert_w_kernel(const float* __restrict__ Wrec,
                                 const float* __restrict__ W_in,
                                 const float* __restrict__ W_out) {
    if (blockIdx.x == 0 && threadIdx.x < kGroups) g_count[threadIdx.x] = 0u;
    const int stride = gridDim.x * blockDim.x;
    const int base   = blockIdx.x * blockDim.x + threadIdx.x;

    for (int idx = base; idx < kH * kH; idx += stride)
        g_Wr[idx] = __float2half_rn(Wrec[idx]);
    for (int idx = base; idx < kH * kI; idx += stride) {
        __nv_bfloat16 hi, lo;
        split_bf16(W_in[idx], hi, lo);
        g_Wi[0][idx] = hi;
        g_Wi[1][idx] = lo;
    }
    for (int idx = base; idx < kO * kH; idx += stride) {
        __half hi, lo;
        split_f16(W_out[idx], hi, lo);
        g_Wout[0][idx] = hi;
        g_Wout[1][idx] = lo;
    }
}

// Prepass: split x into bf16 hi/lo planes (same [B][T][I] layout).
__global__ void convert_x_kernel(const float* __restrict__ x) {
    const int n4 = (kB * kT * kI) / 4;
    __nv_bfloat162* xh = reinterpret_cast<__nv_bfloat162*>(g_xs[0]);
    __nv_bfloat162* xl = reinterpret_cast<__nv_bfloat162*>(g_xs[1]);
    for (int i = blockIdx.x * blockDim.x + threadIdx.x; i < n4;
         i += gridDim.x * blockDim.x) {
        float4 v = reinterpret_cast<const float4*>(x)[i];
        float vs[4] = {v.x, v.y, v.z, v.w};
        __nv_bfloat16 hi[4], lo[4];
#pragma unroll
        for (int k = 0; k < 4; ++k) split_bf16(vs[k], hi[k], lo[k]);
        __nv_bfloat162 p;
        p.x = hi[0]; p.y = hi[1]; xh[2 * i]     = p;
        p.x = hi[2]; p.y = hi[3]; xh[2 * i + 1] = p;
        p.x = lo[0]; p.y = lo[1]; xl[2 * i]     = p;
        p.x = lo[2]; p.y = lo[3]; xl[2 * i + 1] = p;
    }
}

// ---------------------------------------------------------------------------
// xin GEMM: g_xin[r, j] = x[r] @ W_in^T[j] + b_in[j] (bf16 3-pass, unchanged).
// ---------------------------------------------------------------------------
__global__ __launch_bounds__(256, 1)
void xin_gemm_tc(const float* __restrict__ b_in)
{
    extern __shared__ char smem[];
    const int tid = threadIdx.x;
    const int w   = tid >> 5;
    const int l   = tid & 31;
    const int m   = l >> 3;
    const int cb  = blockIdx.x & 7;
    const size_t r0g = (size_t)(blockIdx.x >> 3) * 128;
    const int j0  = cb * 128;

    const int aoff = ((w * 16 + (l & 7) + (m & 1) * 8) * GST + (m >> 1) * 8) * 2;
    const int boff = (((m >> 1) * 8 + (l & 7)) * GST + (m & 1) * 8) * 2;
    const uint32_t bufU[2] = { smem_u32(smem), smem_u32(smem + GBUF) };

    float acc[16][4];
#pragma unroll
    for (int j = 0; j < 16; ++j)
#pragma unroll
        for (int v = 0; v < 4; ++v) acc[j][v] = 0.0f;

    auto load_chunk = [&](int c, uint32_t bu) {
        const int k0 = c * 64;
#pragma unroll
        for (int jj = 0; jj < 8; ++jj) {
            int idx = tid + jj * 256;
            int plane = idx >> 10, rem = idx & 1023;
            int row = rem >> 3, seg = rem & 7;
            cpa16(bu + plane * GPA + (row * GST + seg * 8) * 2,
                  &g_xs[plane][(r0g + row) * kI + k0 + seg * 8]);
        }
#pragma unroll
        for (int jj = 0; jj < 8; ++jj) {
            int idx = tid + jj * 256;
            int plane = idx >> 10, rem = idx & 1023;
            int row = rem >> 3, seg = rem & 7;
            cpa16(bu + 2 * GPA + plane * GPA + (row * GST + seg * 8) * 2,
                  &g_Wi[plane][(size_t)(j0 + row) * kI + k0 + seg * 8]);
        }
    };

    load_chunk(0, bufU[0]);
    cp_commit();
    load_chunk(1, bufU[1]);
    cp_commit();

#pragma unroll 1
    for (int c = 0; c < 2; ++c) {
        if (c == 0) cp_wait1(); else cp_wait0();
        __syncthreads();
        const uint32_t bu  = bufU[c];
        const uint32_t aHi = bu + aoff;
        const uint32_t aLo = bu + GPA + aoff;
        const uint32_t bHi = bu + 2 * GPA + boff;
        const uint32_t bLo = bu + 3 * GPA + boff;
#pragma unroll
        for (int kk = 0; kk < 4; ++kk) {
            uint32_t Ah[4], Al[4];
            ldm4(Ah, aHi + kk * 32);
            ldm4(Al, aLo + kk * 32);
#pragma unroll
            for (int nf = 0; nf < 8; ++nf) {
                uint32_t Bh[4], Bl[4];
                ldm4(Bh, bHi + nf * (16 * GST * 2) + kk * 32);
                ldm4(Bl, bLo + nf * (16 * GST * 2) + kk * 32);
                mma_bf16(acc[2 * nf],     Ah, Bh[0], Bh[1]);
                mma_bf16(acc[2 * nf + 1], Ah, Bh[2], Bh[3]);
                mma_bf16(acc[2 * nf],     Ah, Bl[0], Bl[1]);
                mma_bf16(acc[2 * nf + 1], Ah, Bl[2], Bl[3]);
                mma_bf16(acc[2 * nf],     Al, Bh[0], Bh[1]);
                mma_bf16(acc[2 * nf + 1], Al, Bh[2], Bh[3]);
            }
        }
    }

#pragma unroll
    for (int half = 0; half < 2; ++half) {
        const size_t row = r0g + w * 16 + (l >> 2) + half * 8;
#pragma unroll
        for (int j = 0; j < 16; ++j) {
            const int col = j * 8 + 2 * (l & 3);
            float2 o;
            o.x = acc[j][2 * half + 0] + b_in[j0 + col];
            o.y = acc[j][2 * half + 1] + b_in[j0 + col + 1];
            *reinterpret_cast<float2*>(&g_xin[row * kH + j0 + col]) = o;
        }
    }
}

// ---------------------------------------------------------------------------
// PURE fp16 1-pass tensor-core recurrence (R16 skeleton, W_lo dropped):
//   h stored as single fp16 plane; Wrec single fp16 plane (SMEM-persistent).
//   D += A*B   (8 MMAs + 16 ldm4 per chunk per warp; chunk buffer = A only).
// Monolithic group barrier, 8 chunks of 128, 2-stage cp.async,
// fragment double-buffering.
// Grid: 128 CTAs = 8 groups x 16 N-tiles, 256 thr (8 warps = 2M x 4N).
// ---------------------------------------------------------------------------
__global__ __launch_bounds__(256, 1)
void rnn_rec_tc(float* __restrict__ hid)   // [B, T, H] fp32 output
{
    extern __shared__ char smem[];
    char* sBhi  = smem;                    // persistent Wrec [64][1032] fp16
    char* sBuf0 = smem + BHI_BYTES;
    char* sBuf1 = sBuf0 + BUF_BYTES;

    const int tid = threadIdx.x;
    const int g   = blockIdx.x / kTilesPerGroup;
    const int jt  = blockIdx.x % kTilesPerGroup;
    const int j0  = jt * kTN;
    const int b0  = g * kBc;
    const int w   = tid >> 5;
    const int l   = tid & 31;
    const int r0  = (w >> 2) * 16;   // A-row base within 32-row tile
    const int c0  = (w & 3) * 16;    // n base within 64-col tile

    // ---- persistent Wrec slice load: 64 rows x 128 segs of 8 ----
#pragma unroll
    for (int j = 0; j < 32; ++j) {
        int idx = tid + j * 256;
        int row = idx >> 7, seg = idx & 127;
        cpa16(smem_u32(sBhi + (row * SBHI_STRIDE + seg * 8) * 2),
              &g_Wr[(size_t)(j0 + row) * kH + seg * 8]);
    }
    cp_commit();
    cp_wait0();
    __syncthreads();

    // per-lane ldmatrix offsets (m = l>>3 selects the 8x8 sub-matrix)
    const int m    = l >> 3;
    const int arow = r0 + (l & 7) + (m & 1) * 8;
    const int aoff = (arow * SCH_STRIDE + (m >> 1) * 8) * 2;
    const int brow = c0 + (m >> 1) * 8 + (l & 7);
    const int bhioff = (brow * SBHI_STRIDE + (m & 1) * 8) * 2;

    const uint32_t sBhiU   = smem_u32(sBhi);
    const uint32_t bufU[2] = { smem_u32(sBuf0), smem_u32(sBuf1) };

    // xin / epilogue addressing for this thread
    const int rowA = b0 + r0 + (l >> 2);        // rows rowA, rowA+8
    const int col0 = j0 + c0 + 2 * (l & 3);     // nt=0 col pair
    const int col1 = col0 + 8;                  // nt=1 col pair

    for (int t = 0; t < kT; ++t) {
        // ---- prefetch xin accumulator init (independent of barrier) ----
        const size_t xb0 = ((size_t)rowA * kT + t) * kH;
        const size_t xb8 = ((size_t)(rowA + 8) * kT + t) * kH;
        const float2 x00 = *reinterpret_cast<const float2*>(&g_xin[xb0 + col0]);
        const float2 x01 = *reinterpret_cast<const float2*>(&g_xin[xb0 + col1]);
        const float2 x10 = *reinterpret_cast<const float2*>(&g_xin[xb8 + col0]);
        const float2 x11 = *reinterpret_cast<const float2*>(&g_xin[xb8 + col1]);

        float acc[2][4];
        acc[0][0] = x00.x; acc[0][1] = x00.y; acc[0][2] = x10.x; acc[0][3] = x10.y;
        acc[1][0] = x01.x; acc[1][1] = x01.y; acc[1][2] = x11.x; acc[1][3] = x11.y;

        if (t > 0) {
            // ---- wait for h_{t-1} (group barrier, acquire) ----
            if (tid == 0) {
                const unsigned int target =
                    (unsigned int)(kTilesPerGroup * t);
                while (ld_acquire(&g_count[g]) < target) { }
            }
            __syncthreads();

            // ---- 8 h-chunks (A only), 2-buffer cp.async pipeline ----
            auto load_h_chunk = [&](int c, uint32_t bu) {
#pragma unroll
                for (int jj = 0; jj < 2; ++jj) {   // A: 1 plane x 32r x 16s
                    int idx = tid + jj * 256;
                    int row = idx >> 4, seg = idx & 15;
                    cpa16(bu + (row * SCH_STRIDE + seg * 8) * 2,
                          &g_hb[((size_t)(b0 + row) * kT + (t - 1)) * kH
                                + c * kChunk + seg * 8]);
                }
            };

            load_h_chunk(0, bufU[0]);
            cp_commit();
#pragma unroll 1
            for (int c = 0; c < 8; ++c) {
                if (c < 7) {
                    load_h_chunk(c + 1, bufU[(c + 1) & 1]);
                    cp_commit();
                    cp_wait1();
                } else {
                    cp_wait0();
                }
                __syncthreads();

                const uint32_t bu   = bufU[c & 1];
                const uint32_t aB   = bu + aoff;
                const uint32_t bHiB = sBhiU + bhioff + (c * kChunk) * 2;

                // fragment-pipelined 1-pass MMA loop
                uint32_t Ah[2][4], Bh[2][4];
                ldm4(Ah[0], aB);
                ldm4(Bh[0], bHiB);
#pragma unroll
                for (int kk = 0; kk < 8; ++kk) {
                    const int cur = kk & 1;
                    const int nxt = cur ^ 1;
                    if (kk < 7) {
                        ldm4(Ah[nxt], aB + (kk + 1) * 32);
                        ldm4(Bh[nxt], bHiB + (kk + 1) * 32);
                    }
                    mma_f16(acc[0], Ah[cur], Bh[cur][0], Bh[cur][1]);
                    mma_f16(acc[1], Ah[cur], Bh[cur][2], Bh[cur][3]);
                }
                __syncthreads();   // protect buf before refill
            }
        }

        // ---- epilogue: relu, fp32 hid + single fp16 plane ----
#pragma unroll
        for (int nt = 0; nt < 2; ++nt) {
            const int col = (nt == 0) ? col0 : col1;
#pragma unroll
            for (int half = 0; half < 2; ++half) {
                float v0 = fmaxf(acc[nt][2 * half + 0], 0.0f);
                float v1 = fmaxf(acc[nt][2 * half + 1], 0.0f);
                const int row = rowA + half * 8;
                const size_t o = ((size_t)row * kT + t) * kH + col;
                float2 fv; fv.x = v0; fv.y = v1;
                *reinterpret_cast<float2*>(hid + o) = fv;

                __half2 hp;
                hp.x = __float2half_rn(v0);
                hp.y = __float2half_rn(v1);
                *reinterpret_cast<__half2*>(&g_hb[o]) = hp;
            }
        }

        // order all threads' g_hb stores before the release-arrive
        __syncthreads();
        if (tid == 0) barrier_arrive(&g_count[g]);
    }
}

// ---------------------------------------------------------------------------
// fp16 2-pass output projection + softmax: A = fp16 h (single plane),
// B = W_out fp16 hi+lo. Grid 1024 x 256 thr, CTA = 128 rows x 128 O-cols.
// ---------------------------------------------------------------------------
__global__ __launch_bounds__(256, 1)
void rnn_output_tc(const float* __restrict__ b_out,
                   float* __restrict__ outs)
{
    extern __shared__ char smem[];
    const int tid = threadIdx.x;
    const int w   = tid >> 5;
    const int l   = tid & 31;
    const int m   = l >> 3;
    const size_t r0g = (size_t)blockIdx.x * 128;

    const int aoff = ((w * 16 + (l & 7) + (m & 1) * 8) * GST + (m >> 1) * 8) * 2;
    const int boff = (((m >> 1) * 8 + (l & 7)) * GST + (m & 1) * 8) * 2;
    const uint32_t bufU[2] = { smem_u32(smem), smem_u32(smem + OBUF) };

    float acc[16][4];
#pragma unroll
    for (int j = 0; j < 16; ++j) {
        const int col = j * 8 + 2 * (l & 3);
        float bv0 = b_out[col], bv1 = b_out[col + 1];
        acc[j][0] = bv0; acc[j][1] = bv1; acc[j][2] = bv0; acc[j][3] = bv1;
    }

    auto load_chunk = [&](int c, uint32_t bu) {
        const int k0 = c * 64;
#pragma unroll
        for (int jj = 0; jj < 4; ++jj) {     // A: 1 plane x 128 rows x 8 segs
            int idx = tid + jj * 256;
            int row = idx >> 3, seg = idx & 7;
            cpa16(bu + (row * GST + seg * 8) * 2,
                  &g_hb[(r0g + row) * kH + k0 + seg * 8]);
        }
#pragma unroll
        for (int jj = 0; jj < 8; ++jj) {     // B: 2 planes x 128 n x 8 segs
            int idx = tid + jj * 256;
            int plane = idx >> 10, rem = idx & 1023;
            int row = rem >> 3, seg = rem & 7;
            cpa16(bu + GPA + plane * GPA + (row * GST + seg * 8) * 2,
                  &g_Wout[plane][(size_t)row * kH + k0 + seg * 8]);
        }
    };

    load_chunk(0, bufU[0]);
    cp_commit();

#pragma unroll 1
    for (int c = 0; c < 16; ++c) {
        if (c < 15) {
            load_chunk(c + 1, bufU[(c + 1) & 1]);
            cp_commit();
            cp_wait1();
        } else {
            cp_wait0();
        }
        __syncthreads();

        const uint32_t bu  = bufU[c & 1];
        const uint32_t aB  = bu + aoff;
        const uint32_t bHi = bu + GPA + boff;
        const uint32_t bLo = bu + 2 * GPA + boff;

#pragma unroll
        for (int kk = 0; kk < 4; ++kk) {
            uint32_t Ah[4];
            ldm4(Ah, aB + kk * 32);
#pragma unroll
            for (int nf = 0; nf < 8; ++nf) {
                uint32_t Bh[4], Bl[4];
                ldm4(Bh, bHi + nf * (16 * GST * 2) + kk * 32);
                ldm4(Bl, bLo + nf * (16 * GST * 2) + kk * 32);
                mma_f16(acc[2 * nf],     Ah, Bh[0], Bh[1]);
                mma_f16(acc[2 * nf + 1], Ah, Bh[2], Bh[3]);
                mma_f16(acc[2 * nf],     Ah, Bl[0], Bl[1]);
                mma_f16(acc[2 * nf + 1], Ah, Bl[2], Bl[3]);
            }
        }
        __syncthreads();
    }

#pragma unroll
    for (int half = 0; half < 2; ++half) {
        float mx = -1e30f;
#pragma unroll
        for (int j = 0; j < 16; ++j) {
            mx = fmaxf(mx, acc[j][2 * half + 0]);
            mx = fmaxf(mx, acc[j][2 * half + 1]);
        }
        mx = fmaxf(mx, __shfl_xor_sync(0xffffffffu, mx, 1));
        mx = fmaxf(mx, __shfl_xor_sync(0xffffffffu, mx, 2));

        float e[32], s = 0.0f;
#pragma unroll
        for (int j = 0; j < 16; ++j) {
            e[2 * j]     = expf(acc[j][2 * half + 0] - mx);
            e[2 * j + 1] = expf(acc[j][2 * half + 1] - mx);
            s += e[2 * j] + e[2 * j + 1];
        }
        s += __shfl_xor_sync(0xffffffffu, s, 1);
        s += __shfl_xor_sync(0xffffffffu, s, 2);
        const float inv = 1.0f / s;

        const size_t row = r0g + w * 16 + (l >> 2) + half * 8;
#pragma unroll
        for (int j = 0; j < 16; ++j) {
            float2 o;
            o.x = e[2 * j] * inv;
            o.y = e[2 * j + 1] * inv;
            *reinterpret_cast<float2*>(
                outs + row * kO + j * 8 + 2 * (l & 3)) = o;
        }
    }
}

// ---------------------------------------------------------------------------
// d_in order: x, W_in, b_in, Wrec, W_out, b_out
// d_out: hiddens [B,T,H] fp32 followed by outs [B,T,O] fp32
// ---------------------------------------------------------------------------
extern "C" void kernel_launch(void* const* d_in, const int* in_sizes, int n_in,
                              void* d_out, int out_size) {
    (void)in_sizes; (void)n_in; (void)out_size;
    const float* x     = (const float*)d_in[0];
    const float* W_in  = (const float*)d_in[1];
    const float* b_in  = (const float*)d_in[2];
    const float* Wrec  = (const float*)d_in[3];
    const float* W_out = (const float*)d_in[4];
    const float* b_out = (const float*)d_in[5];

    float* hid  = (float*)d_out;                 // [B,T,H]
    float* outs = hid + (size_t)kB * kT * kH;    // [B,T,O]

    cudaFuncSetAttribute(rnn_rec_tc,
                         cudaFuncAttributeMaxDynamicSharedMemorySize,
                         SMEM_TOTAL);
    cudaFuncSetAttribute(xin_gemm_tc,
                         cudaFuncAttributeMaxDynamicSharedMemorySize, GSMEM);
    cudaFuncSetAttribute(rnn_output_tc,
                         cudaFuncAttributeMaxDynamicSharedMemorySize, OSMEM);

    convert_w_kernel<<<1024, 256>>>(Wrec, W_in, W_out);   // also resets counters
    convert_x_kernel<<<4096, 256>>>(x);
    xin_gemm_tc<<<8192, 256, GSMEM>>>(b_in);
    rnn_rec_tc<<<kGroups * kTilesPerGroup, 256, SMEM_TOTAL>>>(hid);
    rnn_output_tc<<<(kB * kT) / 128, 256, OSMEM>>>(b_out, outs);
}